// round 15
// baseline (speedup 1.0000x reference)
#include <cuda_runtime.h>
#include <cuda_fp16.h>
#include <cstdint>

// ============================ problem dims ============================
static constexpr int B_ = 4, H_ = 8, N_ = 2048, D_ = 64;
static constexpr int BH = B_ * H_;   // 32
static constexpr int BM = 128;       // query rows per CTA (32 per warp)
static constexpr int BN = 64;        // keys per tile
static constexpr int MT = N_ / BM;   // 16
static constexpr int NT = N_ / BN;   // 32

// ==================== pre-converted gmem scratch ======================
// SW128-preswizzled fp16 tile images (hi parts only).
// Q image per (bh, mt): 128 rows x 128B = 16KB. K/V per (bh, nt): 64 x 128B = 8KB.
__device__ __align__(128) uint8_t g_qhi[(size_t)BH * MT * 16384];
__device__ __align__(128) uint8_t g_khi[(size_t)BH * NT * 8192];
__device__ __align__(128) uint8_t g_vhi[(size_t)BH * NT * 8192];
__device__ float g_kk[(size_t)BH * N_];   // -0.125 * log2(e) * ||k||^2 (fp32 K)

// ============================ helpers =============================
__device__ __forceinline__ uint32_t smem_u32(const void* p) {
    uint32_t a;
    asm("{ .reg .u64 t; cvta.to.shared.u64 t, %1; cvt.u32.u64 %0, t; }" : "=r"(a) : "l"(p));
    return a;
}
__device__ __forceinline__ void cpa16(uint32_t s, const void* g) {
    asm volatile("cp.async.cg.shared.global [%0], [%1], 16;" :: "r"(s), "l"(g));
}
__device__ __forceinline__ void cpa_commit() { asm volatile("cp.async.commit_group;" ::: "memory"); }
__device__ __forceinline__ void cpa_wait0()  { asm volatile("cp.async.wait_group 0;" ::: "memory"); }

__device__ __forceinline__ void ldmx4(uint32_t* r, uint32_t a) {
    asm volatile("ldmatrix.sync.aligned.m8n8.x4.shared.b16 {%0,%1,%2,%3}, [%4];"
                 : "=r"(r[0]), "=r"(r[1]), "=r"(r[2]), "=r"(r[3]) : "r"(a));
}
__device__ __forceinline__ void ldmx4t(uint32_t* r, uint32_t a) {
    asm volatile("ldmatrix.sync.aligned.m8n8.x4.trans.shared.b16 {%0,%1,%2,%3}, [%4];"
                 : "=r"(r[0]), "=r"(r[1]), "=r"(r[2]), "=r"(r[3]) : "r"(a));
}
// D += A * B  (m16n8k16, fp16 in, fp32 accum)
__device__ __forceinline__ void mma16816(float* c, const uint32_t* a, uint32_t b0, uint32_t b1) {
    asm volatile("mma.sync.aligned.m16n8k16.row.col.f32.f16.f16.f32 "
                 "{%0,%1,%2,%3}, {%4,%5,%6,%7}, {%8,%9}, {%0,%1,%2,%3};"
                 : "+f"(c[0]), "+f"(c[1]), "+f"(c[2]), "+f"(c[3])
                 : "r"(a[0]), "r"(a[1]), "r"(a[2]), "r"(a[3]), "r"(b0), "r"(b1));
}
__device__ __forceinline__ uint32_t pkhf2(float up, float low) {
    uint32_t d;
    asm("cvt.rn.satfinite.f16x2.f32 %0, %1, %2;" : "=r"(d) : "f"(up), "f"(low));
    return d;
}
__device__ __forceinline__ float ex2f(float x) {
    float y;
    asm("ex2.approx.f32 %0, %1;" : "=f"(y) : "f"(x));
    return y;
}
static constexpr float LOG2E   = 1.4426950408889634f;
static constexpr float SCALE_S = 0.25f * LOG2E;
static constexpr uint32_t ONES2 = 0x3C003C00u;   // fp16 (1.0, 1.0)

// ====================== pre-pass: fp32 -> SW128 fp16 images ======================
__global__ void prep_kernel(const float* __restrict__ q, const float* __restrict__ k,
                            const float* __restrict__ v) {
    int idx  = blockIdx.x * 256 + threadIdx.x;   // 0 .. BH*N*8-1
    int rown = idx >> 3;
    int c    = idx & 7;
    int d0   = c * 8;
    int bh = rown >> 11, n = rown & 2047;

    auto hi8 = [&](const float* src, uint8_t* dh, uint32_t rowoff, float* ss) {
        float xs[8];
        *(float4*)(xs)     = *(const float4*)(src);
        *(float4*)(xs + 4) = *(const float4*)(src + 4);
        uint32_t hp[4];
        #pragma unroll
        for (int j = 0; j < 4; j++) {
            float x0 = xs[2 * j], x1 = xs[2 * j + 1];
            if (ss) *ss += x0 * x0 + x1 * x1;
            hp[j] = pkhf2(x1, x0);
        }
        uint32_t x = rowoff + (uint32_t)d0 * 2;
        uint32_t off = x ^ ((x >> 3) & 0x70);
        *(uint4*)(dh + off) = make_uint4(hp[0], hp[1], hp[2], hp[3]);
    };

    {   // Q (128-row tiles)
        int qmt = n >> 7, r = n & 127;
        hi8(q + (size_t)rown * 64 + d0,
            g_qhi + (((size_t)(bh * MT + qmt)) << 14),
            (uint32_t)r * 128, nullptr);
    }
    {   // K + kk
        int nt = n >> 6, r = n & 63;
        float ss = 0.f;
        hi8(k + (size_t)rown * 64 + d0,
            g_khi + (((size_t)(bh * NT + nt)) << 13),
            (uint32_t)r * 128, &ss);
        ss += __shfl_xor_sync(0xffffffffu, ss, 1);
        ss += __shfl_xor_sync(0xffffffffu, ss, 2);
        ss += __shfl_xor_sync(0xffffffffu, ss, 4);
        if (c == 0) g_kk[rown] = -0.125f * LOG2E * ss;
    }
    {   // V
        int nt = n >> 6, r = n & 63;
        hi8(v + (size_t)rown * 64 + d0,
            g_vhi + (((size_t)(bh * NT + nt)) << 13),
            (uint32_t)r * 128, nullptr);
    }
}

// =========================== main kernel ===========================
// smem: KV ring of 2 x 16KB at [0,32K): khi@0 vhi@8K per buf.
// Q image (16KB) staged at [16K,32K) = buf1's full footprint during the
// prologue, consumed to registers, then buf1 reuses those bytes.
static constexpr uint32_t S_KV  = 0;
static constexpr uint32_t S_QH  = 16384;
static constexpr uint32_t S_KK  = 32768;    // 2 x 256B
static constexpr uint32_t SMEM_BYTES = 32768 + 512;

__global__ __launch_bounds__(128, 3)
void attn_main(float* __restrict__ out) {
    extern __shared__ __align__(1024) uint8_t smem[];
    const uint32_t sb = smem_u32(smem);
    const int tid = threadIdx.x, wid = tid >> 5, lane = tid & 31;
    const int mt = blockIdx.x, bh = blockIdx.y;
    const int b = bh >> 3, h = bh & 7;
    const int mrank = lane >> 3;
    const int l7 = lane & 7;

    // ---- prologue: Q image (staged over buf1) + KV tile 0 -> buf0 ----
    {
        const uint8_t* qh = g_qhi + (((size_t)(bh * MT + mt)) << 14);
        const size_t t0 = ((size_t)(bh * NT)) << 13;
        #pragma unroll
        for (int i = 0; i < 8; i++) {
            int o = (tid + 128 * i) * 16;
            cpa16(sb + S_QH + o, qh + o);
        }
        #pragma unroll
        for (int i = 0; i < 4; i++) {
            int o = (tid + 128 * i) * 16;
            cpa16(sb + S_KV +        o, g_khi + t0 + o);
            cpa16(sb + S_KV + 8192 + o, g_vhi + t0 + o);
        }
        if (tid < 16) cpa16(sb + S_KK + tid * 16, g_kk + (size_t)bh * N_ + tid * 4);
        cpa_commit();
        cpa_wait0();
    }
    __syncthreads();

    // ---- Q A-fragments: 2 m16 blocks per warp (rows wid*32 .. wid*32+31) ----
    uint32_t Qh[2][4][4];
    #pragma unroll
    for (int mb = 0; mb < 2; mb++) {
        int qrow = wid * 32 + mb * 16 + ((mrank & 1) << 3) + l7;
        uint32_t rbase = (uint32_t)qrow * 128;
        uint32_t rx = (uint32_t)((qrow & 7) << 4);
        #pragma unroll
        for (int ks = 0; ks < 4; ks++) {
            uint32_t colb = (uint32_t)(ks * 32 + ((mrank >> 1) << 4));
            ldmx4(Qh[mb][ks], sb + S_QH + rbase + (colb ^ rx));
        }
    }
    __syncthreads();   // Q consumed before buf1 overwrites its bytes

    float O[2][8][4];
    #pragma unroll
    for (int mb = 0; mb < 2; mb++)
        #pragma unroll
        for (int i = 0; i < 8; i++)
            #pragma unroll
            for (int j = 0; j < 4; j++) O[mb][i][j] = 0.f;
    float Lf[2][4] = {{0.f, 0.f, 0.f, 0.f}, {0.f, 0.f, 0.f, 0.f}};

    const int krow16 = ((mrank >> 1) << 3) + l7;
    const int vrow16 = ((mrank & 1) << 3) + l7;
    const uint32_t kcol = (uint32_t)((mrank & 1) << 4);
    const uint32_t vcol = (uint32_t)((mrank >> 1) << 4);

    #pragma unroll 1
    for (int kt = 0; kt < NT; kt++) {
        const uint32_t cb = sb + S_KV + (uint32_t)(kt & 1) * 16384;

        // prefetch tile kt+1 into the other buffer
        if (kt + 1 < NT) {
            const size_t toff = ((size_t)(bh * NT + kt + 1)) << 13;
            const uint32_t dst = sb + S_KV + (uint32_t)((kt + 1) & 1) * 16384;
            #pragma unroll
            for (int i = 0; i < 4; i++) {
                int o = (tid + 128 * i) * 16;
                cpa16(dst +        o, g_khi + toff + o);
                cpa16(dst + 8192 + o, g_vhi + toff + o);
            }
            if (tid < 16) cpa16(sb + S_KK + ((kt + 1) & 1) * 256 + tid * 16,
                                g_kk + (size_t)bh * N_ + (size_t)(kt + 1) * 64 + tid * 4);
            cpa_commit();
        }

        const float* kkp = (const float*)(smem + S_KK + (kt & 1) * 256);

        // ---- per 16-key block: S -> softmax -> L-MMA -> PV (transient S, P) ----
        #pragma unroll
        for (int np = 0; np < 4; np++) {
            float S[2][2][4];
            #pragma unroll
            for (int mb = 0; mb < 2; mb++)
                #pragma unroll
                for (int t = 0; t < 2; t++)
                    #pragma unroll
                    for (int j = 0; j < 4; j++) S[mb][t][j] = 0.f;

            {   // S block: 4 LDSM (K), 16 MMAs
                const int row = np * 16 + krow16;
                const uint32_t rowa = cb + (uint32_t)row * 128;
                const uint32_t rx = (uint32_t)((row & 7) << 4);
                #pragma unroll
                for (int ks = 0; ks < 4; ks++) {
                    uint32_t a = rowa + (((uint32_t)(ks * 32) + kcol) ^ rx);
                    uint32_t KBh[4];
                    ldmx4(KBh, a);
                    #pragma unroll
                    for (int mb = 0; mb < 2; mb++) {
                        mma16816(S[mb][0], Qh[mb][ks], KBh[0], KBh[1]);
                        mma16816(S[mb][1], Qh[mb][ks], KBh[2], KBh[3]);
                    }
                }
            }

            // softmax numerator -> single fp16 P A-fragments + L via P.ones
            uint32_t Ph[2][4];
            #pragma unroll
            for (int mb = 0; mb < 2; mb++) {
                #pragma unroll
                for (int t = 0; t < 2; t++) {
                    const int col = np * 16 + t * 8 + 2 * (lane & 3);
                    float k0 = kkp[col], k1 = kkp[col + 1];
                    float p0 = ex2f(fmaf(SCALE_S, S[mb][t][0], k0));
                    float p1 = ex2f(fmaf(SCALE_S, S[mb][t][1], k1));
                    float p2 = ex2f(fmaf(SCALE_S, S[mb][t][2], k0));
                    float p3 = ex2f(fmaf(SCALE_S, S[mb][t][3], k1));
                    Ph[mb][t * 2]     = pkhf2(p1, p0);
                    Ph[mb][t * 2 + 1] = pkhf2(p3, p2);
                }
                mma16816(Lf[mb], Ph[mb], ONES2, ONES2);
            }

            {   // PV block: 4 LDSM (V), 16 MMAs
                const int row = np * 16 + vrow16;
                const uint32_t rowa = cb + 8192 + (uint32_t)row * 128;
                const uint32_t rx = (uint32_t)((row & 7) << 4);
                #pragma unroll
                for (int dp = 0; dp < 4; dp++) {
                    uint32_t a = rowa + (((uint32_t)(dp * 32) + vcol) ^ rx);
                    uint32_t VBh[4];
                    ldmx4t(VBh, a);
                    #pragma unroll
                    for (int mb = 0; mb < 2; mb++) {
                        mma16816(O[mb][2 * dp],     Ph[mb], VBh[0], VBh[1]);
                        mma16816(O[mb][2 * dp + 1], Ph[mb], VBh[2], VBh[3]);
                    }
                }
            }
        }

        if (kt + 1 < NT) {
            cpa_wait0();
            __syncthreads();
        }
    }

    // ---- epilogue: normalize (L per-row in Lf), store both m-blocks ----
    #pragma unroll
    for (int mb = 0; mb < 2; mb++) {
        float inv0 = 1.0f / Lf[mb][0];
        float inv1 = 1.0f / Lf[mb][2];

        const int r0 = mt * BM + wid * 32 + mb * 16 + (lane >> 2);
        const int dbase = 2 * (lane & 3);
        float* o0 = out + (((size_t)(b * N_ + r0) * H_ + h) << 6);
        float* o1 = out + (((size_t)(b * N_ + r0 + 8) * H_ + h) << 6);
        #pragma unroll
        for (int dt = 0; dt < 8; dt++) {
            int d = dt * 8 + dbase;
            float2 a0 = make_float2(O[mb][dt][0] * inv0, O[mb][dt][1] * inv0);
            float2 a1 = make_float2(O[mb][dt][2] * inv1, O[mb][dt][3] * inv1);
            *(float2*)(o0 + d) = a0;
            *(float2*)(o1 + d) = a1;
        }
    }
}

// ============================ launch ============================
extern "C" void kernel_launch(void* const* d_in, const int* in_sizes, int n_in,
                              void* d_out, int out_size) {
    (void)in_sizes; (void)n_in; (void)out_size;
    const float* q = (const float*)d_in[0];
    const float* k = (const float*)d_in[1];
    const float* v = (const float*)d_in[2];
    float* out = (float*)d_out;

    prep_kernel<<<BH * N_ * 8 / 256, 256>>>(q, k, v);

    cudaFuncSetAttribute(attn_main, cudaFuncAttributeMaxDynamicSharedMemorySize, SMEM_BYTES);
    dim3 grid(MT, BH);
    attn_main<<<grid, 128, SMEM_BYTES>>>(out);
}

// round 16
// speedup vs baseline: 1.0637x; 1.0637x over previous
#include <cuda_runtime.h>
#include <cuda_fp16.h>
#include <cstdint>

// ============================ problem dims ============================
static constexpr int B_ = 4, H_ = 8, N_ = 2048, D_ = 64;
static constexpr int BH = B_ * H_;   // 32
static constexpr int BM = 128;       // query rows per cluster (32 per warp)
static constexpr int BN = 64;        // keys per tile
static constexpr int MT = N_ / BM;   // 16
static constexpr int NT = N_ / BN;   // 32
static constexpr int TILES_PER_RANK = NT / 2;   // 16

// ==================== pre-converted gmem scratch ======================
// SW128-preswizzled fp16 tile images (hi parts only).
__device__ __align__(128) uint8_t g_qhi[(size_t)BH * MT * 16384];
__device__ __align__(128) uint8_t g_khi[(size_t)BH * NT * 8192];
__device__ __align__(128) uint8_t g_vhi[(size_t)BH * NT * 8192];
__device__ float g_kk[(size_t)BH * N_];   // -0.125 * log2(e) * ||k||^2 (fp32 K)

// ============================ helpers =============================
__device__ __forceinline__ uint32_t smem_u32(const void* p) {
    uint32_t a;
    asm("{ .reg .u64 t; cvta.to.shared.u64 t, %1; cvt.u32.u64 %0, t; }" : "=r"(a) : "l"(p));
    return a;
}
__device__ __forceinline__ void cpa16(uint32_t s, const void* g) {
    asm volatile("cp.async.cg.shared.global [%0], [%1], 16;" :: "r"(s), "l"(g));
}
__device__ __forceinline__ void cpa_commit() { asm volatile("cp.async.commit_group;" ::: "memory"); }
__device__ __forceinline__ void cpa_wait0()  { asm volatile("cp.async.wait_group 0;" ::: "memory"); }

__device__ __forceinline__ void ldmx4(uint32_t* r, uint32_t a) {
    asm volatile("ldmatrix.sync.aligned.m8n8.x4.shared.b16 {%0,%1,%2,%3}, [%4];"
                 : "=r"(r[0]), "=r"(r[1]), "=r"(r[2]), "=r"(r[3]) : "r"(a));
}
__device__ __forceinline__ void ldmx4t(uint32_t* r, uint32_t a) {
    asm volatile("ldmatrix.sync.aligned.m8n8.x4.trans.shared.b16 {%0,%1,%2,%3}, [%4];"
                 : "=r"(r[0]), "=r"(r[1]), "=r"(r[2]), "=r"(r[3]) : "r"(a));
}
__device__ __forceinline__ void mma16816(float* c, const uint32_t* a, uint32_t b0, uint32_t b1) {
    asm volatile("mma.sync.aligned.m16n8k16.row.col.f32.f16.f16.f32 "
                 "{%0,%1,%2,%3}, {%4,%5,%6,%7}, {%8,%9}, {%0,%1,%2,%3};"
                 : "+f"(c[0]), "+f"(c[1]), "+f"(c[2]), "+f"(c[3])
                 : "r"(a[0]), "r"(a[1]), "r"(a[2]), "r"(a[3]), "r"(b0), "r"(b1));
}
__device__ __forceinline__ uint32_t pkhf2(float up, float low) {
    uint32_t d;
    asm("cvt.rn.satfinite.f16x2.f32 %0, %1, %2;" : "=r"(d) : "f"(up), "f"(low));
    return d;
}
__device__ __forceinline__ float ex2f(float x) {
    float y;
    asm("ex2.approx.f32 %0, %1;" : "=f"(y) : "f"(x));
    return y;
}
static constexpr float LOG2E   = 1.4426950408889634f;
static constexpr float SCALE_S = 0.25f * LOG2E;
static constexpr uint32_t ONES2 = 0x3C003C00u;   // fp16 (1.0, 1.0)

#define CLUSTER_SYNC() do { \
    asm volatile("barrier.cluster.arrive.aligned;" ::: "memory"); \
    asm volatile("barrier.cluster.wait.aligned;" ::: "memory"); \
} while (0)

// ====================== pre-pass: fp32 -> SW128 fp16 images ======================
__global__ void prep_kernel(const float* __restrict__ q, const float* __restrict__ k,
                            const float* __restrict__ v) {
    int idx  = blockIdx.x * 256 + threadIdx.x;   // 0 .. BH*N*8-1
    int rown = idx >> 3;
    int c    = idx & 7;
    int d0   = c * 8;
    int bh = rown >> 11, n = rown & 2047;

    auto hi8 = [&](const float* src, uint8_t* dh, uint32_t rowoff, float* ss) {
        float xs[8];
        *(float4*)(xs)     = *(const float4*)(src);
        *(float4*)(xs + 4) = *(const float4*)(src + 4);
        uint32_t hp[4];
        #pragma unroll
        for (int j = 0; j < 4; j++) {
            float x0 = xs[2 * j], x1 = xs[2 * j + 1];
            if (ss) *ss += x0 * x0 + x1 * x1;
            hp[j] = pkhf2(x1, x0);
        }
        uint32_t x = rowoff + (uint32_t)d0 * 2;
        uint32_t off = x ^ ((x >> 3) & 0x70);
        *(uint4*)(dh + off) = make_uint4(hp[0], hp[1], hp[2], hp[3]);
    };

    {   // Q (128-row tiles)
        int qmt = n >> 7, r = n & 127;
        hi8(q + (size_t)rown * 64 + d0,
            g_qhi + (((size_t)(bh * MT + qmt)) << 14),
            (uint32_t)r * 128, nullptr);
    }
    {   // K + kk
        int nt = n >> 6, r = n & 63;
        float ss = 0.f;
        hi8(k + (size_t)rown * 64 + d0,
            g_khi + (((size_t)(bh * NT + nt)) << 13),
            (uint32_t)r * 128, &ss);
        ss += __shfl_xor_sync(0xffffffffu, ss, 1);
        ss += __shfl_xor_sync(0xffffffffu, ss, 2);
        ss += __shfl_xor_sync(0xffffffffu, ss, 4);
        if (c == 0) g_kk[rown] = -0.125f * LOG2E * ss;
    }
    {   // V
        int nt = n >> 6, r = n & 63;
        hi8(v + (size_t)rown * 64 + d0,
            g_vhi + (((size_t)(bh * NT + nt)) << 13),
            (uint32_t)r * 128, nullptr);
    }
}

// =========================== main kernel ===========================
// smem: KV ring of 2 x 16KB at [0,32K): khi@0 vhi@8K per buf.
// Q image (16KB) staged at [16K,32K) = buf1's footprint during prologue.
// After the loop the whole [0,32K) is dead -> used as the cluster-combine
// O buffer (128 rows x 64 f32 = 32KB); remote L goes into the dead kk area.
static constexpr uint32_t S_KV  = 0;
static constexpr uint32_t S_QH  = 16384;
static constexpr uint32_t S_KK  = 32768;    // 2 x 256B (dead after loop -> remote L)
static constexpr uint32_t SMEM_BYTES = 32768 + 512;

__global__ __launch_bounds__(128, 3) __cluster_dims__(2, 1, 1)
void attn_main(float* __restrict__ out) {
    extern __shared__ __align__(1024) uint8_t smem[];
    const uint32_t sb = smem_u32(smem);
    const int tid = threadIdx.x, wid = tid >> 5, lane = tid & 31;
    const int rank = blockIdx.x;              // split-K rank (0/1)
    const int mt = blockIdx.y, bh = blockIdx.z;
    const int b = bh >> 3, h = bh & 7;
    const int kt0 = rank * TILES_PER_RANK;
    const int mrank = lane >> 3;
    const int l7 = lane & 7;

    // ---- prologue: Q image (staged over buf1) + KV tile kt0 -> buf0 ----
    {
        const uint8_t* qh = g_qhi + (((size_t)(bh * MT + mt)) << 14);
        const size_t t0 = ((size_t)(bh * NT + kt0)) << 13;
        #pragma unroll
        for (int i = 0; i < 8; i++) {
            int o = (tid + 128 * i) * 16;
            cpa16(sb + S_QH + o, qh + o);
        }
        #pragma unroll
        for (int i = 0; i < 4; i++) {
            int o = (tid + 128 * i) * 16;
            cpa16(sb + S_KV +        o, g_khi + t0 + o);
            cpa16(sb + S_KV + 8192 + o, g_vhi + t0 + o);
        }
        if (tid < 16) cpa16(sb + S_KK + tid * 16,
                            g_kk + (size_t)bh * N_ + (size_t)kt0 * 64 + tid * 4);
        cpa_commit();
        cpa_wait0();
    }
    __syncthreads();

    // ---- Q A-fragments: 2 m16 blocks per warp ----
    uint32_t Qh[2][4][4];
    #pragma unroll
    for (int mb = 0; mb < 2; mb++) {
        int qrow = wid * 32 + mb * 16 + ((mrank & 1) << 3) + l7;
        uint32_t rbase = (uint32_t)qrow * 128;
        uint32_t rx = (uint32_t)((qrow & 7) << 4);
        #pragma unroll
        for (int ks = 0; ks < 4; ks++) {
            uint32_t colb = (uint32_t)(ks * 32 + ((mrank >> 1) << 4));
            ldmx4(Qh[mb][ks], sb + S_QH + rbase + (colb ^ rx));
        }
    }
    __syncthreads();   // Q consumed before buf1 overwrites its bytes

    float O[2][8][4];
    #pragma unroll
    for (int mb = 0; mb < 2; mb++)
        #pragma unroll
        for (int i = 0; i < 8; i++)
            #pragma unroll
            for (int j = 0; j < 4; j++) O[mb][i][j] = 0.f;
    float Lf[2][4] = {{0.f, 0.f, 0.f, 0.f}, {0.f, 0.f, 0.f, 0.f}};

    const int krow16 = ((mrank >> 1) << 3) + l7;
    const int vrow16 = ((mrank & 1) << 3) + l7;
    const uint32_t kcol = (uint32_t)((mrank & 1) << 4);
    const uint32_t vcol = (uint32_t)((mrank >> 1) << 4);

    #pragma unroll 1
    for (int lt = 0; lt < TILES_PER_RANK; lt++) {
        const int kt = kt0 + lt;
        const uint32_t cb = sb + S_KV + (uint32_t)(lt & 1) * 16384;

        // prefetch tile kt+1 into the other buffer
        if (lt + 1 < TILES_PER_RANK) {
            const size_t toff = ((size_t)(bh * NT + kt + 1)) << 13;
            const uint32_t dst = sb + S_KV + (uint32_t)((lt + 1) & 1) * 16384;
            #pragma unroll
            for (int i = 0; i < 4; i++) {
                int o = (tid + 128 * i) * 16;
                cpa16(dst +        o, g_khi + toff + o);
                cpa16(dst + 8192 + o, g_vhi + toff + o);
            }
            if (tid < 16) cpa16(sb + S_KK + ((lt + 1) & 1) * 256 + tid * 16,
                                g_kk + (size_t)bh * N_ + (size_t)(kt + 1) * 64 + tid * 4);
            cpa_commit();
        }

        const float* kkp = (const float*)(smem + S_KK + (lt & 1) * 256);

        // ---- per 16-key block: S -> softmax -> L-MMA -> PV ----
        #pragma unroll
        for (int np = 0; np < 4; np++) {
            float S[2][2][4];
            #pragma unroll
            for (int mb = 0; mb < 2; mb++)
                #pragma unroll
                for (int t = 0; t < 2; t++)
                    #pragma unroll
                    for (int j = 0; j < 4; j++) S[mb][t][j] = 0.f;

            {   // S block: 4 LDSM (K), 16 MMAs
                const int row = np * 16 + krow16;
                const uint32_t rowa = cb + (uint32_t)row * 128;
                const uint32_t rx = (uint32_t)((row & 7) << 4);
                #pragma unroll
                for (int ks = 0; ks < 4; ks++) {
                    uint32_t a = rowa + (((uint32_t)(ks * 32) + kcol) ^ rx);
                    uint32_t KBh[4];
                    ldmx4(KBh, a);
                    #pragma unroll
                    for (int mb = 0; mb < 2; mb++) {
                        mma16816(S[mb][0], Qh[mb][ks], KBh[0], KBh[1]);
                        mma16816(S[mb][1], Qh[mb][ks], KBh[2], KBh[3]);
                    }
                }
            }

            // softmax numerator -> fp16 P fragments + L via P.ones
            uint32_t Ph[2][4];
            #pragma unroll
            for (int mb = 0; mb < 2; mb++) {
                #pragma unroll
                for (int t = 0; t < 2; t++) {
                    const int col = np * 16 + t * 8 + 2 * (lane & 3);
                    float k0 = kkp[col], k1 = kkp[col + 1];
                    float p0 = ex2f(fmaf(SCALE_S, S[mb][t][0], k0));
                    float p1 = ex2f(fmaf(SCALE_S, S[mb][t][1], k1));
                    float p2 = ex2f(fmaf(SCALE_S, S[mb][t][2], k0));
                    float p3 = ex2f(fmaf(SCALE_S, S[mb][t][3], k1));
                    Ph[mb][t * 2]     = pkhf2(p1, p0);
                    Ph[mb][t * 2 + 1] = pkhf2(p3, p2);
                }
                mma16816(Lf[mb], Ph[mb], ONES2, ONES2);
            }

            {   // PV block: 4 LDSM (V), 16 MMAs
                const int row = np * 16 + vrow16;
                const uint32_t rowa = cb + 8192 + (uint32_t)row * 128;
                const uint32_t rx = (uint32_t)((row & 7) << 4);
                #pragma unroll
                for (int dp = 0; dp < 4; dp++) {
                    uint32_t a = rowa + (((uint32_t)(dp * 32) + vcol) ^ rx);
                    uint32_t VBh[4];
                    ldmx4t(VBh, a);
                    #pragma unroll
                    for (int mb = 0; mb < 2; mb++) {
                        mma16816(O[mb][2 * dp],     Ph[mb], VBh[0], VBh[1]);
                        mma16816(O[mb][2 * dp + 1], Ph[mb], VBh[2], VBh[3]);
                    }
                }
            }
        }

        if (lt + 1 < TILES_PER_RANK) {
            cpa_wait0();
            __syncthreads();
        }
    }

    // ---- cluster combine: rank1 pushes O (unnormalized) + L into rank0 smem ----
    const int dbase = 2 * (lane & 3);
    CLUSTER_SYNC();   // both ranks done -> rank0's KV/Q smem is dead

    if (rank == 1) {
        #pragma unroll
        for (int mb = 0; mb < 2; mb++) {
            const int r0l = wid * 32 + mb * 16 + (lane >> 2);
            #pragma unroll
            for (int dt = 0; dt < 8; dt++) {
                int d = dt * 8 + dbase;
                uint32_t a0 = sb + (uint32_t)((r0l * 64 + d) * 4);
                uint32_t a1 = sb + (uint32_t)(((r0l + 8) * 64 + d) * 4);
                uint32_t ra0, ra1;
                asm("mapa.shared::cluster.u32 %0, %1, 0;" : "=r"(ra0) : "r"(a0));
                asm("mapa.shared::cluster.u32 %0, %1, 0;" : "=r"(ra1) : "r"(a1));
                unsigned long long p0, p1;
                asm("mov.b64 %0, {%1,%2};" : "=l"(p0) : "f"(O[mb][dt][0]), "f"(O[mb][dt][1]));
                asm("mov.b64 %0, {%1,%2};" : "=l"(p1) : "f"(O[mb][dt][2]), "f"(O[mb][dt][3]));
                asm volatile("st.shared::cluster.b64 [%0], %1;" :: "r"(ra0), "l"(p0) : "memory");
                asm volatile("st.shared::cluster.b64 [%0], %1;" :: "r"(ra1), "l"(p1) : "memory");
            }
            if ((lane & 3) == 0) {
                uint32_t la0 = sb + S_KK + (uint32_t)(r0l * 4);
                uint32_t la1 = sb + S_KK + (uint32_t)((r0l + 8) * 4);
                uint32_t rl0, rl1;
                asm("mapa.shared::cluster.u32 %0, %1, 0;" : "=r"(rl0) : "r"(la0));
                asm("mapa.shared::cluster.u32 %0, %1, 0;" : "=r"(rl1) : "r"(la1));
                asm volatile("st.shared::cluster.f32 [%0], %1;" :: "r"(rl0), "f"(Lf[mb][0]) : "memory");
                asm volatile("st.shared::cluster.f32 [%0], %1;" :: "r"(rl1), "f"(Lf[mb][2]) : "memory");
            }
        }
    }

    CLUSTER_SYNC();   // remote stores visible to rank0

    if (rank == 0) {
        const float* Or = (const float*)smem;
        const float* Lr = (const float*)(smem + S_KK);
        #pragma unroll
        for (int mb = 0; mb < 2; mb++) {
            const int r0l = wid * 32 + mb * 16 + (lane >> 2);
            float inv0 = 1.0f / (Lf[mb][0] + Lr[r0l]);
            float inv1 = 1.0f / (Lf[mb][2] + Lr[r0l + 8]);

            const int r0 = mt * BM + r0l;
            float* o0 = out + (((size_t)(b * N_ + r0) * H_ + h) << 6);
            float* o1 = out + (((size_t)(b * N_ + r0 + 8) * H_ + h) << 6);
            #pragma unroll
            for (int dt = 0; dt < 8; dt++) {
                int d = dt * 8 + dbase;
                float2 q0 = *(const float2*)(Or + r0l * 64 + d);
                float2 q1 = *(const float2*)(Or + (r0l + 8) * 64 + d);
                float2 a0 = make_float2((O[mb][dt][0] + q0.x) * inv0, (O[mb][dt][1] + q0.y) * inv0);
                float2 a1 = make_float2((O[mb][dt][2] + q1.x) * inv1, (O[mb][dt][3] + q1.y) * inv1);
                *(float2*)(o0 + d) = a0;
                *(float2*)(o1 + d) = a1;
            }
        }
    }
}

// ============================ launch ============================
extern "C" void kernel_launch(void* const* d_in, const int* in_sizes, int n_in,
                              void* d_out, int out_size) {
    (void)in_sizes; (void)n_in; (void)out_size;
    const float* q = (const float*)d_in[0];
    const float* k = (const float*)d_in[1];
    const float* v = (const float*)d_in[2];
    float* out = (float*)d_out;

    prep_kernel<<<BH * N_ * 8 / 256, 256>>>(q, k, v);

    cudaFuncSetAttribute(attn_main, cudaFuncAttributeMaxDynamicSharedMemorySize, SMEM_BYTES);
    dim3 grid(2, MT, BH);   // cluster dim x = 2 (split-K ranks)
    attn_main<<<grid, 128, SMEM_BYTES>>>(out);
}

// round 17
// speedup vs baseline: 1.1247x; 1.0574x over previous
#include <cuda_runtime.h>
#include <cuda_fp16.h>
#include <cstdint>

// ============================ problem dims ============================
static constexpr int B_ = 4, H_ = 8, N_ = 2048, D_ = 64;
static constexpr int BH = B_ * H_;   // 32
static constexpr int BM = 64;        // query rows per CTA (16 per warp)
static constexpr int BN = 128;       // keys per tile
static constexpr int MT = N_ / BM;   // 32
static constexpr int NT = N_ / BN;   // 16

// ==================== pre-converted gmem scratch ======================
// SW128-preswizzled fp16 tile images (hi parts only).
// Q image per (bh, mt): 64 rows x 128B = 8KB. K/V per (bh, nt): 128 x 128B = 16KB.
__device__ __align__(128) uint8_t g_qhi[(size_t)BH * MT * 8192];
__device__ __align__(128) uint8_t g_khi[(size_t)BH * NT * 16384];
__device__ __align__(128) uint8_t g_vhi[(size_t)BH * NT * 16384];
__device__ float g_kk[(size_t)BH * N_];   // -0.125 * log2(e) * ||k||^2 (fp32 K)

// ============================ helpers =============================
__device__ __forceinline__ uint32_t smem_u32(const void* p) {
    uint32_t a;
    asm("{ .reg .u64 t; cvta.to.shared.u64 t, %1; cvt.u32.u64 %0, t; }" : "=r"(a) : "l"(p));
    return a;
}
__device__ __forceinline__ void cpa16(uint32_t s, const void* g) {
    asm volatile("cp.async.cg.shared.global [%0], [%1], 16;" :: "r"(s), "l"(g));
}
__device__ __forceinline__ void cpa_commit() { asm volatile("cp.async.commit_group;" ::: "memory"); }
__device__ __forceinline__ void cpa_wait0()  { asm volatile("cp.async.wait_group 0;" ::: "memory"); }

__device__ __forceinline__ void ldmx4(uint32_t* r, uint32_t a) {
    asm volatile("ldmatrix.sync.aligned.m8n8.x4.shared.b16 {%0,%1,%2,%3}, [%4];"
                 : "=r"(r[0]), "=r"(r[1]), "=r"(r[2]), "=r"(r[3]) : "r"(a));
}
__device__ __forceinline__ void ldmx4t(uint32_t* r, uint32_t a) {
    asm volatile("ldmatrix.sync.aligned.m8n8.x4.trans.shared.b16 {%0,%1,%2,%3}, [%4];"
                 : "=r"(r[0]), "=r"(r[1]), "=r"(r[2]), "=r"(r[3]) : "r"(a));
}
// D += A * B  (m16n8k16, fp16 in, fp32 accum)
__device__ __forceinline__ void mma16816(float* c, const uint32_t* a, uint32_t b0, uint32_t b1) {
    asm volatile("mma.sync.aligned.m16n8k16.row.col.f32.f16.f16.f32 "
                 "{%0,%1,%2,%3}, {%4,%5,%6,%7}, {%8,%9}, {%0,%1,%2,%3};"
                 : "+f"(c[0]), "+f"(c[1]), "+f"(c[2]), "+f"(c[3])
                 : "r"(a[0]), "r"(a[1]), "r"(a[2]), "r"(a[3]), "r"(b0), "r"(b1));
}
__device__ __forceinline__ uint32_t pkhf2(float up, float low) {
    uint32_t d;
    asm("cvt.rn.satfinite.f16x2.f32 %0, %1, %2;" : "=r"(d) : "f"(up), "f"(low));
    return d;
}
__device__ __forceinline__ float ex2f(float x) {
    float y;
    asm("ex2.approx.f32 %0, %1;" : "=f"(y) : "f"(x));
    return y;
}
static constexpr float LOG2E   = 1.4426950408889634f;
static constexpr float SCALE_S = 0.25f * LOG2E;
static constexpr uint32_t ONES2 = 0x3C003C00u;   // fp16 (1.0, 1.0)

// ====================== pre-pass: fp32 -> SW128 fp16 images ======================
__global__ void prep_kernel(const float* __restrict__ q, const float* __restrict__ k,
                            const float* __restrict__ v) {
    int idx  = blockIdx.x * 256 + threadIdx.x;   // 0 .. BH*N*8-1
    int rown = idx >> 3;
    int c    = idx & 7;
    int d0   = c * 8;
    int bh = rown >> 11, n = rown & 2047;

    auto hi8 = [&](const float* src, uint8_t* dh, uint32_t rowoff, float* ss) {
        float xs[8];
        *(float4*)(xs)     = *(const float4*)(src);
        *(float4*)(xs + 4) = *(const float4*)(src + 4);
        uint32_t hp[4];
        #pragma unroll
        for (int j = 0; j < 4; j++) {
            float x0 = xs[2 * j], x1 = xs[2 * j + 1];
            if (ss) *ss += x0 * x0 + x1 * x1;
            hp[j] = pkhf2(x1, x0);
        }
        uint32_t x = rowoff + (uint32_t)d0 * 2;
        uint32_t off = x ^ ((x >> 3) & 0x70);
        *(uint4*)(dh + off) = make_uint4(hp[0], hp[1], hp[2], hp[3]);
    };

    {   // Q (64-row tiles)
        int qmt = n >> 6, r = n & 63;
        hi8(q + (size_t)rown * 64 + d0,
            g_qhi + (((size_t)(bh * MT + qmt)) << 13),
            (uint32_t)r * 128, nullptr);
    }
    {   // K + kk (128-row tiles)
        int nt = n >> 7, r = n & 127;
        float ss = 0.f;
        hi8(k + (size_t)rown * 64 + d0,
            g_khi + (((size_t)(bh * NT + nt)) << 14),
            (uint32_t)r * 128, &ss);
        ss += __shfl_xor_sync(0xffffffffu, ss, 1);
        ss += __shfl_xor_sync(0xffffffffu, ss, 2);
        ss += __shfl_xor_sync(0xffffffffu, ss, 4);
        if (c == 0) g_kk[rown] = -0.125f * LOG2E * ss;
    }
    {   // V (128-row tiles)
        int nt = n >> 7, r = n & 127;
        hi8(v + (size_t)rown * 64 + d0,
            g_vhi + (((size_t)(bh * NT + nt)) << 14),
            (uint32_t)r * 128, nullptr);
    }
}

// =========================== main kernel ===========================
// smem: KV ring of 2 x 32KB at [0,64K): khi@0 vhi@16K per buf.
// Q image (8KB) staged at [32K,40K) = buf1's khi footprint during the
// prologue, consumed to registers, then buf1 reuses those bytes.
static constexpr uint32_t S_KV  = 0;
static constexpr uint32_t S_QH  = 32768;
static constexpr uint32_t S_KK  = 65536;    // 2 x 512B
static constexpr uint32_t SMEM_BYTES = 65536 + 1024;

__global__ __launch_bounds__(128, 3)
void attn_main(float* __restrict__ out) {
    extern __shared__ __align__(1024) uint8_t smem[];
    const uint32_t sb = smem_u32(smem);
    const int tid = threadIdx.x, wid = tid >> 5, lane = tid & 31;
    const int mt = blockIdx.x, bh = blockIdx.y;
    const int b = bh >> 3, h = bh & 7;
    const int mrank = lane >> 3;
    const int l7 = lane & 7;

    // ---- prologue: Q image (staged over buf1's khi) + KV tile 0 -> buf0 ----
    {
        const uint8_t* qh = g_qhi + (((size_t)(bh * MT + mt)) << 13);
        const size_t t0 = ((size_t)(bh * NT)) << 14;
        #pragma unroll
        for (int i = 0; i < 4; i++) {
            int o = (tid + 128 * i) * 16;
            cpa16(sb + S_QH + o, qh + o);
        }
        #pragma unroll
        for (int i = 0; i < 8; i++) {
            int o = (tid + 128 * i) * 16;
            cpa16(sb + S_KV +         o, g_khi + t0 + o);
            cpa16(sb + S_KV + 16384 + o, g_vhi + t0 + o);
        }
        if (tid < 32) cpa16(sb + S_KK + tid * 16, g_kk + (size_t)bh * N_ + tid * 4);
        cpa_commit();
        cpa_wait0();
    }
    __syncthreads();

    // ---- Q A-fragments (persist in registers) ----
    uint32_t Qh[4][4];
    {
        int qrow = wid * 16 + ((mrank & 1) << 3) + l7;
        uint32_t rbase = (uint32_t)qrow * 128;
        uint32_t rx = (uint32_t)((qrow & 7) << 4);
        #pragma unroll
        for (int ks = 0; ks < 4; ks++) {
            uint32_t colb = (uint32_t)(ks * 32 + ((mrank >> 1) << 4));
            ldmx4(Qh[ks], sb + S_QH + rbase + (colb ^ rx));
        }
    }
    __syncthreads();   // Q consumed before buf1 overwrites its bytes

    float O[8][4];
    #pragma unroll
    for (int i = 0; i < 8; i++)
        #pragma unroll
        for (int j = 0; j < 4; j++) O[i][j] = 0.f;
    float Lf[4] = {0.f, 0.f, 0.f, 0.f};   // L via P.ones MMA (rows r, r+8)

    const int krow16 = ((mrank >> 1) << 3) + l7;
    const int vrow16 = ((mrank & 1) << 3) + l7;
    const uint32_t kcol = (uint32_t)((mrank & 1) << 4);
    const uint32_t vcol = (uint32_t)((mrank >> 1) << 4);

    #pragma unroll 1
    for (int kt = 0; kt < NT; kt++) {
        const uint32_t cb = sb + S_KV + (uint32_t)(kt & 1) * 32768;

        // prefetch tile kt+1 into the other buffer
        if (kt + 1 < NT) {
            const size_t toff = ((size_t)(bh * NT + kt + 1)) << 14;
            const uint32_t dst = sb + S_KV + (uint32_t)((kt + 1) & 1) * 32768;
            #pragma unroll
            for (int i = 0; i < 8; i++) {
                int o = (tid + 128 * i) * 16;
                cpa16(dst +         o, g_khi + toff + o);
                cpa16(dst + 16384 + o, g_vhi + toff + o);
            }
            if (tid < 32) cpa16(sb + S_KK + ((kt + 1) & 1) * 512 + tid * 16,
                                g_kk + (size_t)bh * N_ + (size_t)(kt + 1) * 128 + tid * 4);
            cpa_commit();
        }

        const float* kkp = (const float*)(smem + S_KK + (kt & 1) * 512);

        // ---- per 16-key block: S -> softmax -> L-MMA -> PV (transient S, P) ----
        #pragma unroll
        for (int np = 0; np < 8; np++) {
            float S[2][4];
            #pragma unroll
            for (int t = 0; t < 2; t++)
                #pragma unroll
                for (int j = 0; j < 4; j++) S[t][j] = 0.f;

            {   // S block: 4 LDSM, 8 MMAs
                const int row = np * 16 + krow16;
                const uint32_t rowa = cb + (uint32_t)row * 128;
                const uint32_t rx = (uint32_t)((row & 7) << 4);
                #pragma unroll
                for (int ks = 0; ks < 4; ks++) {
                    uint32_t a = rowa + (((uint32_t)(ks * 32) + kcol) ^ rx);
                    uint32_t KBh[4];
                    ldmx4(KBh, a);
                    mma16816(S[0], Qh[ks], KBh[0], KBh[1]);
                    mma16816(S[1], Qh[ks], KBh[2], KBh[3]);
                }
            }

            // softmax numerator -> single fp16 P A-fragment (4 regs)
            uint32_t Ph[4];
            #pragma unroll
            for (int t = 0; t < 2; t++) {
                const int col = np * 16 + t * 8 + 2 * (lane & 3);
                float k0 = kkp[col], k1 = kkp[col + 1];
                float p0 = ex2f(fmaf(SCALE_S, S[t][0], k0));
                float p1 = ex2f(fmaf(SCALE_S, S[t][1], k1));
                float p2 = ex2f(fmaf(SCALE_S, S[t][2], k0));
                float p3 = ex2f(fmaf(SCALE_S, S[t][3], k1));
                Ph[t * 2]     = pkhf2(p1, p0);
                Ph[t * 2 + 1] = pkhf2(p3, p2);
            }

            // L += P . ones (1 MMA; rows land in Lf[0]=r, Lf[2]=r+8)
            mma16816(Lf, Ph, ONES2, ONES2);

            {   // PV block: 4 LDSM, 8 MMAs
                const int row = np * 16 + vrow16;
                const uint32_t rowa = cb + 16384 + (uint32_t)row * 128;
                const uint32_t rx = (uint32_t)((row & 7) << 4);
                #pragma unroll
                for (int dp = 0; dp < 4; dp++) {
                    uint32_t a = rowa + (((uint32_t)(dp * 32) + vcol) ^ rx);
                    uint32_t VBh[4];
                    ldmx4t(VBh, a);
                    mma16816(O[2 * dp],     Ph, VBh[0], VBh[1]);
                    mma16816(O[2 * dp + 1], Ph, VBh[2], VBh[3]);
                }
            }
        }

        if (kt + 1 < NT) {
            cpa_wait0();
            __syncthreads();
        }
    }

    // ---- epilogue: normalize (L per-row in Lf), store ----
    float inv0 = 1.0f / Lf[0];
    float inv1 = 1.0f / Lf[2];

    const int r0 = mt * BM + wid * 16 + (lane >> 2);
    const int dbase = 2 * (lane & 3);
    float* o0 = out + (((size_t)(b * N_ + r0) * H_ + h) << 6);
    float* o1 = out + (((size_t)(b * N_ + r0 + 8) * H_ + h) << 6);
    #pragma unroll
    for (int dt = 0; dt < 8; dt++) {
        int d = dt * 8 + dbase;
        float2 a0 = make_float2(O[dt][0] * inv0, O[dt][1] * inv0);
        float2 a1 = make_float2(O[dt][2] * inv1, O[dt][3] * inv1);
        *(float2*)(o0 + d) = a0;
        *(float2*)(o1 + d) = a1;
    }
}

// ============================ launch ============================
extern "C" void kernel_launch(void* const* d_in, const int* in_sizes, int n_in,
                              void* d_out, int out_size) {
    (void)in_sizes; (void)n_in; (void)out_size;
    const float* q = (const float*)d_in[0];
    const float* k = (const float*)d_in[1];
    const float* v = (const float*)d_in[2];
    float* out = (float*)d_out;

    prep_kernel<<<BH * N_ * 8 / 256, 256>>>(q, k, v);

    cudaFuncSetAttribute(attn_main, cudaFuncAttributeMaxDynamicSharedMemorySize, SMEM_BYTES);
    dim3 grid(MT, BH);
    attn_main<<<grid, 128, SMEM_BYTES>>>(out);
}